// round 2
// baseline (speedup 1.0000x reference)
#include <cuda_runtime.h>

// FPN Pooler: multi-level ROIAlign
// feats: f0 [2,256,200,200], f1 [2,256,100,100], f2 [2,256,50,50], f3 [2,256,25,25]
// boxes [1000,4], img_ids [1000] -> out [1000,256,7,7] fp32

#define POOL_OUT 7
#define POOL_SR  2
#define POOL_P   14          // OUT*SR
#define POOL_C   256
#define ITEMS_PER_BOX (POOL_C * POOL_OUT * POOL_OUT)   // 12544

struct LevelInfo { int H, W; float scale; };

__global__ __launch_bounds__(256) void pooler_kernel(
    const float* __restrict__ f0,
    const float* __restrict__ f1,
    const float* __restrict__ f2,
    const float* __restrict__ f3,
    const float* __restrict__ boxes,
    const int*   __restrict__ img_ids,
    float* __restrict__ out)
{
    const int n = blockIdx.x;

    // geometry (separable, channel-independent)
    __shared__ int   s_ro0[POOL_P], s_ro1[POOL_P];   // y0*W, y1*W
    __shared__ int   s_x0[POOL_P],  s_x1[POOL_P];
    __shared__ float s_ly[POOL_P],  s_lx[POOL_P];
    __shared__ float s_vy[POOL_P],  s_vx[POOL_P];
    __shared__ const float* s_base;   // feat[lvl] + img*C*H*W
    __shared__ int s_HW;

    if (threadIdx.x == 0) {
        const float bx1 = boxes[4*n + 0];
        const float by1 = boxes[4*n + 1];
        const float bx2 = boxes[4*n + 2];
        const float by2 = boxes[4*n + 3];

        // level mapping (match f32 JAX formula exactly)
        const float area = (bx2 - bx1) * (by2 - by1);
        const float s    = sqrtf(area);
        float lf = floorf(4.0f + log2f(s / 224.0f + 1e-6f));
        lf = fminf(fmaxf(lf, 2.0f), 5.0f);
        const int lvl = (int)lf - 2;

        LevelInfo L;
        const float* fp;
        switch (lvl) {
            case 0:  L = {200, 200, 0.25f};    fp = f0; break;
            case 1:  L = {100, 100, 0.125f};   fp = f1; break;
            case 2:  L = {50,  50,  0.0625f};  fp = f2; break;
            default: L = {25,  25,  0.03125f}; fp = f3; break;
        }
        const int img = img_ids[n];
        const int HW  = L.H * L.W;
        s_base = fp + (size_t)img * POOL_C * HW;
        s_HW   = HW;

        const float x1 = bx1 * L.scale;
        const float y1 = by1 * L.scale;
        const float x2 = bx2 * L.scale;
        const float y2 = by2 * L.scale;
        const float roi_w = fmaxf(x2 - x1, 1.0f);
        const float roi_h = fmaxf(y2 - y1, 1.0f);
        const float bw = roi_w / (float)POOL_OUT;
        const float bh = roi_h / (float)POOL_OUT;

        #pragma unroll
        for (int i = 0; i < POOL_P; ++i) {
            const int p = i >> 1;       // output index
            const int r = i & 1;        // sub-sample index
            // y axis
            {
                const float yg = y1 + (float)p * bh + ((float)r + 0.5f) * bh * 0.5f;
                const float vy = (yg >= -1.0f && yg <= (float)L.H) ? 1.0f : 0.0f;
                float y = fminf(fmaxf(yg, 0.0f), (float)(L.H - 1));
                int y0i = (int)floorf(y);
                int y1i = min(y0i + 1, L.H - 1);
                s_ro0[i] = y0i * L.W;
                s_ro1[i] = y1i * L.W;
                s_ly[i]  = y - (float)y0i;
                s_vy[i]  = vy;
            }
            // x axis
            {
                const float xg = x1 + (float)p * bw + ((float)r + 0.5f) * bw * 0.5f;
                const float vx = (xg >= -1.0f && xg <= (float)L.W) ? 1.0f : 0.0f;
                float x = fminf(fmaxf(xg, 0.0f), (float)(L.W - 1));
                int x0i = (int)floorf(x);
                int x1i = min(x0i + 1, L.W - 1);
                s_x0[i] = x0i;
                s_x1[i] = x1i;
                s_lx[i] = x - (float)x0i;
                s_vx[i] = vx;
            }
        }
    }
    __syncthreads();

    const float* base = s_base;
    const int HW = s_HW;
    float* out_n = out + (size_t)n * ITEMS_PER_BOX;

    // 12544 items / 256 threads = exactly 49 per thread.
    // Consecutive tids -> consecutive bins within a channel (warp stays
    // inside one channel plane => sector sharing, coalesced stores).
    #pragma unroll 1
    for (int i = 0; i < 49; ++i) {
        const int idx = threadIdx.x + (i << 8);
        const int c   = idx / 49;
        const int k   = idx - c * 49;
        const int ph  = k / 7;
        const int pw  = k - ph * 7;

        const float* fc = base + (size_t)c * HW;
        float acc = 0.0f;

        #pragma unroll
        for (int sy = 0; sy < 2; ++sy) {
            const int iy = ph * 2 + sy;
            const int ro0 = s_ro0[iy];
            const int ro1 = s_ro1[iy];
            const float ly = s_ly[iy];
            const float hy = 1.0f - ly;
            const float vy = s_vy[iy];
            #pragma unroll
            for (int sx = 0; sx < 2; ++sx) {
                const int ix = pw * 2 + sx;
                const int c0 = s_x0[ix];
                const int c1 = s_x1[ix];
                const float lx = s_lx[ix];
                const float hx = 1.0f - lx;
                const float v  = vy * s_vx[ix];

                const float v00 = __ldg(fc + ro0 + c0);
                const float v01 = __ldg(fc + ro0 + c1);
                const float v10 = __ldg(fc + ro1 + c0);
                const float v11 = __ldg(fc + ro1 + c1);

                const float val = hy * (hx * v00 + lx * v01)
                                + ly * (hx * v10 + lx * v11);
                acc = fmaf(v, val, acc);
            }
        }
        out_n[idx] = acc * 0.25f;
    }
}

extern "C" void kernel_launch(void* const* d_in, const int* in_sizes, int n_in,
                              void* d_out, int out_size)
{
    const float* f0    = (const float*)d_in[0];
    const float* f1    = (const float*)d_in[1];
    const float* f2    = (const float*)d_in[2];
    const float* f3    = (const float*)d_in[3];
    const float* boxes = (const float*)d_in[4];
    const int*   imgs  = (const int*)d_in[5];
    float* out = (float*)d_out;

    const int N = in_sizes[4] / 4;   // 1000 boxes
    pooler_kernel<<<N, 256>>>(f0, f1, f2, f3, boxes, imgs, out);
}